// round 6
// baseline (speedup 1.0000x reference)
#include <cuda_runtime.h>
#include <cuda_bf16.h>
#include <float.h>

#define Bc   8
#define Lc   2048
#define IND  1024
#define Dc   64
#define Hc   2
#define DH   32
#define NNc  32
#define TI   16

// scratch buffers (no allocations allowed -> __device__ globals)
__device__ float g_xa[Bc * Lc * Dc];
__device__ float g_xb[Bc * Lc * Dc];
__device__ float g_attn[Bc * Lc * Dc];
__device__ int   g_top[Bc * Lc * NNc];

// ---------------------------------------------------------------------------
// Top-32 smallest dist per (b,i) row (== 32 largest dw; stable ties -> low idx)
// ---------------------------------------------------------------------------
__global__ void topk_kernel(const float* __restrict__ dist,
                            const float* __restrict__ mask,
                            int* __restrict__ top) {
    __shared__ float key[Lc];
    __shared__ float rv[8];
    __shared__ int   ri[8];
    int row = blockIdx.x;            // 0..B*L-1
    int b   = row / Lc;
    int t   = threadIdx.x;           // 256 threads

    for (int j = t; j < Lc; j += 256) {
        float m = mask[b * Lc + j];
        float d = dist[(size_t)row * Lc + j];
        // masked columns have dw = 0 -> rank after all unmasked; dist in [0,1)
        key[j] = (m > 0.f) ? d : 3.0f;
    }
    __syncthreads();

    for (int k = 0; k < NNc; k++) {
        float bv = FLT_MAX;
        int   bi = 0x7fffffff;
        for (int j = t; j < Lc; j += 256) {
            float v = key[j];
            if (v < bv || (v == bv && j < bi)) { bv = v; bi = j; }
        }
        #pragma unroll
        for (int o = 16; o; o >>= 1) {
            float ov = __shfl_xor_sync(0xffffffffu, bv, o);
            int   oi = __shfl_xor_sync(0xffffffffu, bi, o);
            if (ov < bv || (ov == bv && oi < bi)) { bv = ov; bi = oi; }
        }
        if ((t & 31) == 0) { rv[t >> 5] = bv; ri[t >> 5] = bi; }
        __syncthreads();
        if (t == 0) {
            float fv = rv[0]; int fi = ri[0];
            #pragma unroll
            for (int w = 1; w < 8; w++) {
                if (rv[w] < fv || (rv[w] == fv && ri[w] < fi)) { fv = rv[w]; fi = ri[w]; }
            }
            top[(size_t)row * NNc + k] = fi;
            key[fi] = FLT_MAX;
        }
        __syncthreads();
    }
}

// ---------------------------------------------------------------------------
// Fused front-end: LN(1024) -> x@w_in -> leaky -> LN(64) -> @w_h -> leaky -> LN(64)
// 8 rows per block, 256 threads.
// ---------------------------------------------------------------------------
__global__ void mlp_kernel(const float* __restrict__ node,
                           const float* __restrict__ gin, const float* __restrict__ bin,
                           const float* __restrict__ w_in, const float* __restrict__ bias_in,
                           const float* __restrict__ g1, const float* __restrict__ b1,
                           const float* __restrict__ w_h, const float* __restrict__ bias_h,
                           const float* __restrict__ g2, const float* __restrict__ b2,
                           float* __restrict__ out) {
    __shared__ float xs[8][IND];        // 32 KB
    __shared__ float red[4][8][Dc];     // 8 KB
    __shared__ float h[8][Dc];          // 2 KB

    int t = threadIdx.x;
    int w = t >> 5, lane = t & 31;
    size_t row0 = (size_t)blockIdx.x * 8;

    // ---- input LN: warp per row ----
    {
        size_t row = row0 + w;
        const float* xr = node + row * IND;
        float vals[IND / 32];
        float s = 0.f;
        #pragma unroll
        for (int k = 0; k < IND / 32; k++) {
            float v = xr[lane + 32 * k];
            vals[k] = v; s += v;
        }
        #pragma unroll
        for (int o = 16; o; o >>= 1) s += __shfl_xor_sync(0xffffffffu, s, o);
        float mean = s * (1.f / IND);
        float vs = 0.f;
        #pragma unroll
        for (int k = 0; k < IND / 32; k++) { float d = vals[k] - mean; vs += d * d; }
        #pragma unroll
        for (int o = 16; o; o >>= 1) vs += __shfl_xor_sync(0xffffffffu, vs, o);
        float rstd = rsqrtf(vs * (1.f / IND) + 1e-5f);
        #pragma unroll
        for (int k = 0; k < IND / 32; k++) {
            int i = lane + 32 * k;
            xs[w][i] = (vals[k] - mean) * rstd * gin[i] + bin[i];
        }
    }
    __syncthreads();

    // ---- GEMM1: 1024 -> 64, 8 rows at once ----
    {
        int o = t & 63, quad = t >> 6;
        float acc[8];
        #pragma unroll
        for (int r = 0; r < 8; r++) acc[r] = 0.f;
        int i0 = quad * 256;
        for (int i = i0; i < i0 + 256; i++) {
            float wv = w_in[i * Dc + o];
            #pragma unroll
            for (int r = 0; r < 8; r++) acc[r] += xs[r][i] * wv;
        }
        #pragma unroll
        for (int r = 0; r < 8; r++) red[quad][r][o] = acc[r];
    }
    __syncthreads();
    for (int p = t; p < 8 * Dc; p += 256) {
        int r = p >> 6, o = p & 63;
        float v = red[0][r][o] + red[1][r][o] + red[2][r][o] + red[3][r][o] + bias_in[o];
        h[r][o] = v > 0.f ? v : 0.01f * v;
    }
    __syncthreads();

    // ---- LN h1: warp per row ----
    {
        float a = h[w][lane], c = h[w][lane + 32];
        float s = a + c;
        #pragma unroll
        for (int o = 16; o; o >>= 1) s += __shfl_xor_sync(0xffffffffu, s, o);
        float mean = s * (1.f / 64.f);
        float da = a - mean, dc = c - mean;
        float vv = da * da + dc * dc;
        #pragma unroll
        for (int o = 16; o; o >>= 1) vv += __shfl_xor_sync(0xffffffffu, vv, o);
        float rstd = rsqrtf(vv * (1.f / 64.f) + 1e-5f);
        h[w][lane]      = da * rstd * g1[lane] + b1[lane];
        h[w][lane + 32] = dc * rstd * g1[lane + 32] + b1[lane + 32];
    }
    __syncthreads();

    // ---- GEMM2: 64 -> 64 ----
    float h2tmp[2];
    #pragma unroll
    for (int pp = 0; pp < 2; pp++) {
        int p = t + pp * 256;
        int r = p >> 6, o = p & 63;
        float acc = bias_h[o];
        #pragma unroll
        for (int i = 0; i < Dc; i++) acc += h[r][i] * w_h[i * Dc + o];
        h2tmp[pp] = acc > 0.f ? acc : 0.01f * acc;
    }
    __syncthreads();
    #pragma unroll
    for (int pp = 0; pp < 2; pp++) {
        int p = t + pp * 256;
        h[p >> 6][p & 63] = h2tmp[pp];
    }
    __syncthreads();

    // ---- LN h2 + write out ----
    {
        float a = h[w][lane], c = h[w][lane + 32];
        float s = a + c;
        #pragma unroll
        for (int o = 16; o; o >>= 1) s += __shfl_xor_sync(0xffffffffu, s, o);
        float mean = s * (1.f / 64.f);
        float da = a - mean, dc = c - mean;
        float vv = da * da + dc * dc;
        #pragma unroll
        for (int o = 16; o; o >>= 1) vv += __shfl_xor_sync(0xffffffffu, vv, o);
        float rstd = rsqrtf(vv * (1.f / 64.f) + 1e-5f);
        size_t row = row0 + w;
        out[row * Dc + lane]      = da * rstd * g2[lane] + b2[lane];
        out[row * Dc + lane + 32] = dc * rstd * g2[lane + 32] + b2[lane + 32];
    }
}

// ---------------------------------------------------------------------------
// Attention: per block, TI=16 query rows of one (b,h) slice. Full-row scores
// in smem (needed for exact softmax Z), then sparse top-32 PV gather.
// out = (sum_{j in top} e_j * h_j) / (sum_top e + 1e-5 * Z)   [raw, pre-LN]
// ---------------------------------------------------------------------------
__global__ void attn_kernel(const float* __restrict__ x,
                            const float* __restrict__ mask,
                            const int* __restrict__ top,
                            float* __restrict__ out) {
    extern __shared__ float sm[];
    float* s    = sm;                    // TI * L
    float* hi   = s + TI * Lc;           // TI * 32
    float* mrow = hi + TI * DH;          // TI
    float* zrow = mrow + TI;             // TI
    float* wred = zrow + TI;             // 8 * TI

    int t = threadIdx.x;                 // 256
    int slice = blockIdx.y;              // b*H + h
    int b = slice >> 1, hh = slice & 1;
    int i0 = blockIdx.x * TI;
    const float* xb = x + (size_t)b * Lc * Dc + hh * DH;   // row j: xb + j*64

    // load query tile
    for (int p = t; p < TI * DH; p += 256) {
        int r = p >> 5, d = p & 31;
        hi[p] = xb[(size_t)(i0 + r) * Dc + d];
    }
    __syncthreads();

    // pass 1: scores + running max
    float tmax[TI];
    #pragma unroll
    for (int r = 0; r < TI; r++) tmax[r] = -FLT_MAX;

    for (int jj = 0; jj < Lc / 256; jj++) {
        int j = jj * 256 + t;
        const float4* hj4 = (const float4*)(xb + (size_t)j * Dc);
        float4 aj[8];
        #pragma unroll
        for (int q = 0; q < 8; q++) aj[q] = hj4[q];
        float am = (1.f - mask[b * Lc + j]) * -10000.f;
        #pragma unroll
        for (int r = 0; r < TI; r++) {
            const float4* hir = (const float4*)(hi + r * DH);
            float acc = 0.f;
            #pragma unroll
            for (int q = 0; q < 8; q++) {
                float4 hv = hir[q];
                acc += hv.x * aj[q].x + hv.y * aj[q].y + hv.z * aj[q].z + hv.w * aj[q].w;
            }
            float sc = acc + am;
            s[r * Lc + j] = sc;
            tmax[r] = fmaxf(tmax[r], sc);
        }
    }
    // reduce row max across block
    #pragma unroll
    for (int r = 0; r < TI; r++) {
        #pragma unroll
        for (int o = 16; o; o >>= 1)
            tmax[r] = fmaxf(tmax[r], __shfl_xor_sync(0xffffffffu, tmax[r], o));
    }
    if ((t & 31) == 0) {
        #pragma unroll
        for (int r = 0; r < TI; r++) wred[(t >> 5) * TI + r] = tmax[r];
    }
    __syncthreads();
    if (t < TI) {
        float m = wred[t];
        #pragma unroll
        for (int w = 1; w < 8; w++) m = fmaxf(m, wred[w * TI + t]);
        mrow[t] = m;
    }
    __syncthreads();

    // pass 2: Z = sum exp(s - m). 16 threads per row.
    {
        int r = t >> 4, l = t & 15;
        float m = mrow[r];
        float z = 0.f;
        for (int k = 0; k < Lc / 16; k++)
            z += __expf(s[r * Lc + l + k * 16] - m);
        #pragma unroll
        for (int o = 8; o; o >>= 1) z += __shfl_xor_sync(0xffffffffu, z, o);
        if (l == 0) zrow[r] = z;
    }
    __syncthreads();

    // pass 3: sparse PV. Warp w handles rows 2w, 2w+1; lane = output dim.
    int w = t >> 5, d = t & 31;
    #pragma unroll
    for (int rr = 0; rr < 2; rr++) {
        int r = 2 * w + rr;
        int i = i0 + r;
        int idx = top[((size_t)(b * Lc + i)) * NNc + d];
        float e = __expf(s[r * Lc + idx] - mrow[r]);
        float st = e;
        #pragma unroll
        for (int o = 16; o; o >>= 1) st += __shfl_xor_sync(0xffffffffu, st, o);
        float denom = st + 1e-5f * zrow[r];
        float acc = 0.f;
        #pragma unroll
        for (int k = 0; k < 32; k++) {
            float ek = __shfl_sync(0xffffffffu, e, k);
            int   jk = __shfl_sync(0xffffffffu, idx, k);
            acc += ek * xb[(size_t)jk * Dc + d];
        }
        out[(size_t)(b * Lc + i) * Dc + hh * DH + d] = acc / denom;
    }
}

// ---------------------------------------------------------------------------
// LN over 64 (warp per row)
// ---------------------------------------------------------------------------
__global__ void ln_kernel(const float* __restrict__ in,
                          const float* __restrict__ g, const float* __restrict__ bt,
                          float* __restrict__ out) {
    int t = threadIdx.x, w = t >> 5, lane = t & 31;
    size_t row = (size_t)blockIdx.x * 8 + w;
    float a = in[row * Dc + lane], c = in[row * Dc + lane + 32];
    float s = a + c;
    #pragma unroll
    for (int o = 16; o; o >>= 1) s += __shfl_xor_sync(0xffffffffu, s, o);
    float mean = s * (1.f / 64.f);
    float da = a - mean, dc = c - mean;
    float vv = da * da + dc * dc;
    #pragma unroll
    for (int o = 16; o; o >>= 1) vv += __shfl_xor_sync(0xffffffffu, vv, o);
    float rstd = rsqrtf(vv * (1.f / 64.f) + 1e-5f);
    out[row * Dc + lane]      = da * rstd * g[lane] + bt[lane];
    out[row * Dc + lane + 32] = dc * rstd * g[lane + 32] + bt[lane + 32];
}

// LN + final projection to scalar
__global__ void ln_proj_kernel(const float* __restrict__ in,
                               const float* __restrict__ g, const float* __restrict__ bt,
                               const float* __restrict__ wo, const float* __restrict__ bo,
                               float* __restrict__ y) {
    int t = threadIdx.x, w = t >> 5, lane = t & 31;
    size_t row = (size_t)blockIdx.x * 8 + w;
    float a = in[row * Dc + lane], c = in[row * Dc + lane + 32];
    float s = a + c;
    #pragma unroll
    for (int o = 16; o; o >>= 1) s += __shfl_xor_sync(0xffffffffu, s, o);
    float mean = s * (1.f / 64.f);
    float da = a - mean, dc = c - mean;
    float vv = da * da + dc * dc;
    #pragma unroll
    for (int o = 16; o; o >>= 1) vv += __shfl_xor_sync(0xffffffffu, vv, o);
    float rstd = rsqrtf(vv * (1.f / 64.f) + 1e-5f);
    float na = da * rstd * g[lane] + bt[lane];
    float nc = dc * rstd * g[lane + 32] + bt[lane + 32];
    float contrib = na * wo[lane] + nc * wo[lane + 32];
    #pragma unroll
    for (int o = 16; o; o >>= 1) contrib += __shfl_xor_sync(0xffffffffu, contrib, o);
    if (lane == 0) y[row] = contrib + bo[0];
}

// ---------------------------------------------------------------------------
extern "C" void kernel_launch(void* const* d_in, const int* in_sizes, int n_in,
                              void* d_out, int out_size) {
    const float* node  = (const float*)d_in[0];
    // d_in[1] = edge features, unused by the reference graph
    const float* dist  = (const float*)d_in[2];
    const float* mask  = (const float*)d_in[3];
    const float* ln_in_g = (const float*)d_in[4];
    const float* ln_in_b = (const float*)d_in[5];
    const float* w_in    = (const float*)d_in[6];
    const float* b_in    = (const float*)d_in[7];
    const float* g1      = (const float*)d_in[8];
    const float* b1      = (const float*)d_in[9];
    const float* w_h     = (const float*)d_in[10];
    const float* b_h     = (const float*)d_in[11];
    const float* g2      = (const float*)d_in[12];
    const float* b2      = (const float*)d_in[13];
    const float* a0g     = (const float*)d_in[14];
    const float* a0b     = (const float*)d_in[15];
    const float* a1g     = (const float*)d_in[16];
    const float* a1b     = (const float*)d_in[17];
    const float* w_out   = (const float*)d_in[18];
    const float* b_out   = (const float*)d_in[19];
    float* y = (float*)d_out;

    void *pxa, *pxb, *pattn, *ptop;
    cudaGetSymbolAddress(&pxa, g_xa);
    cudaGetSymbolAddress(&pxb, g_xb);
    cudaGetSymbolAddress(&pattn, g_attn);
    cudaGetSymbolAddress(&ptop, g_top);
    float* xa   = (float*)pxa;
    float* xb   = (float*)pxb;
    float* attn = (float*)pattn;
    int*   topi = (int*)ptop;

    const int ATTN_SMEM = (TI * Lc + TI * DH + TI + TI + 8 * TI) * sizeof(float);
    cudaFuncSetAttribute(attn_kernel, cudaFuncAttributeMaxDynamicSharedMemorySize, ATTN_SMEM);

    topk_kernel<<<Bc * Lc, 256>>>(dist, mask, topi);
    mlp_kernel<<<Bc * Lc / 8, 256>>>(node, ln_in_g, ln_in_b, w_in, b_in,
                                     g1, b1, w_h, b_h, g2, b2, xa);

    dim3 agrid(Lc / TI, Bc * Hc);
    attn_kernel<<<agrid, 256, ATTN_SMEM>>>(xa, mask, topi, attn);
    ln_kernel<<<Bc * Lc / 8, 256>>>(attn, a0g, a0b, xb);
    attn_kernel<<<agrid, 256, ATTN_SMEM>>>(xb, mask, topi, attn);
    ln_proj_kernel<<<Bc * Lc / 8, 256>>>(attn, a1g, a1b, w_out, b_out, y);
}